// round 15
// baseline (speedup 1.0000x reference)
#include <cuda_runtime.h>
#include <cuda_fp16.h>
#include <math.h>

#define N_NODES 50000
#define N_EDGES 800000
#define F_DIM   128
#define F4      32      // float4 per feature row
#define HID     256
#define NCLS    40

#define SCAN_BLOCKS ((N_NODES + 255) / 256)   // 196

// ---------------- device scratch (static: no allocation allowed) ----------------
// RULE (learned R3-R5): never pass __device__ symbol addresses from host code —
// on GB300 the host-side shadow resolves via ATS to HOST memory. All buffer
// selection happens inside device code.
__device__ int      g_deg[N_NODES];
__device__ int      g_rowstart[N_NODES + 1];
__device__ int      g_cursor[N_NODES];
__device__ int      g_bsum[SCAN_BLOCKS];
__device__ float    g_norm[N_NODES];
__device__ unsigned g_csr[N_EDGES];          // (src << 16) | fp16(norm[src]) bits
__device__ __half   g_xh0[N_NODES * F_DIM];  // fp16 ping
__device__ __half   g_xh1[N_NODES * F_DIM];  // fp16 pong; holds final fp16 y
__device__ __half   g_yh [N_NODES * F_DIM];  // fp16 running sum (fp32 math)
__device__ __half2  g_w1p[(F_DIM / 2) * HID];   // W1 packed (k,k+1) pairs
__device__ __half2  g_w2p[(HID / 2) * NCLS];    // W2 packed (k,k+1) pairs

// ---------------- build: degree ----------------
__global__ void zero_deg_kernel() {
    int i = blockIdx.x * blockDim.x + threadIdx.x;
    if (i < N_NODES) g_deg[i] = 0;
}

__global__ void deg_kernel(const int4* __restrict__ dst4) {
    int i = blockIdx.x * blockDim.x + threadIdx.x;
    if (i < N_EDGES / 4) {
        int4 d = dst4[i];
        atomicAdd(&g_deg[d.x], 1);
        atomicAdd(&g_deg[d.y], 1);
        atomicAdd(&g_deg[d.z], 1);
        atomicAdd(&g_deg[d.w], 1);
    }
}

// ---------------- hierarchical scan ----------------
__device__ __forceinline__ int warp_incl_scan(int v, int lane) {
#pragma unroll
    for (int o = 1; o < 32; o <<= 1) {
        int n = __shfl_up_sync(0xffffffffu, v, o);
        if (lane >= o) v += n;
    }
    return v;
}

__device__ __forceinline__ int block_incl_scan_256(int v, int tid) {
    __shared__ int ws[8];
    int lane = tid & 31, w = tid >> 5;
    int incl = warp_incl_scan(v, lane);
    if (lane == 31) ws[w] = incl;
    __syncthreads();
    if (w == 0) {
        int s = (lane < 8) ? ws[lane] : 0;
        s = warp_incl_scan(s, lane);
        if (lane < 8) ws[lane] = s;
    }
    __syncthreads();
    if (w > 0) incl += ws[w - 1];
    return incl;
}

__global__ void scan1_kernel() {
    int tid = threadIdx.x;
    int i = blockIdx.x * 256 + tid;
    int v = (i < N_NODES) ? g_deg[i] : 0;
    if (i < N_NODES) g_norm[i] = rsqrtf((float)(v < 1 ? 1 : v));
    int incl = block_incl_scan_256(v, tid);
    if (i < N_NODES) g_rowstart[i] = incl - v;
    if (tid == 255) g_bsum[blockIdx.x] = incl;
}

// phase 2: blocks < SCAN_BLOCKS do offset fixup; ALL blocks (grid-stride)
// convert features to fp16 and pack W1/W2 into fp16 pair layout
__global__ void scan3_kernel(const float4* __restrict__ feat,
                             const float* __restrict__ W1,
                             const float* __restrict__ W2) {
    __shared__ int ssum[8];
    int tid = threadIdx.x;
    int bid = blockIdx.x;
    int lane = tid & 31, w = tid >> 5;

    if (bid < SCAN_BLOCKS) {
        int v = (tid < bid && tid < SCAN_BLOCKS) ? g_bsum[tid] : 0;
#pragma unroll
        for (int o = 16; o > 0; o >>= 1) v += __shfl_down_sync(0xffffffffu, v, o);
        if (lane == 0) ssum[w] = v;
        __syncthreads();
        if (tid == 0) {
            int s = 0;
#pragma unroll
            for (int i = 0; i < 8; i++) s += ssum[i];
            ssum[0] = s;
        }
        __syncthreads();
        int off = ssum[0];

        int i = bid * 256 + tid;
        if (i < N_NODES) {
            int r = g_rowstart[i] + off;
            g_rowstart[i] = r;
            g_cursor[i]   = r;
        }
        if (i == 0) g_rowstart[N_NODES] = N_EDGES;
    }

    int gid = bid * 256 + tid;
    int stride = gridDim.x * 256;

    // grid-stride fp16 conversion of features
    uint2* xh0v = (uint2*)g_xh0;
    for (int j = gid; j < N_NODES * F4; j += stride) {
        float4 f = feat[j];
        __half2 h0 = __floats2half2_rn(f.x, f.y);
        __half2 h1 = __floats2half2_rn(f.z, f.w);
        uint2 u;
        u.x = *(unsigned*)&h0;
        u.y = *(unsigned*)&h1;
        xh0v[j] = u;
    }
    // pack W1 -> (k,k+1)-pair fp16 layout [F_DIM/2][HID]
    for (int j = gid; j < (F_DIM / 2) * HID; j += stride) {
        int p = j / HID, n = j - p * HID;
        g_w1p[j] = __floats2half2_rn(W1[(2 * p) * HID + n], W1[(2 * p + 1) * HID + n]);
    }
    // pack W2 -> [HID/2][NCLS]
    for (int j = gid; j < (HID / 2) * NCLS; j += stride) {
        int p = j / NCLS, n = j - p * NCLS;
        g_w2p[j] = __floats2half2_rn(W2[(2 * p) * NCLS + n], W2[(2 * p + 1) * NCLS + n]);
    }
}

// fill CSR: packed (src<<16)|fp16(norm[src]), int4 edge loads
__device__ __forceinline__ unsigned pack_edge(int s) {
    __half hw = __float2half_rn(g_norm[s]);
    return ((unsigned)s << 16) | (unsigned)__half_as_ushort(hw);
}

__global__ void fill_kernel(const int4* __restrict__ src4, const int4* __restrict__ dst4) {
    int i = blockIdx.x * blockDim.x + threadIdx.x;
    if (i < N_EDGES / 4) {
        int4 s = src4[i];
        int4 d = dst4[i];
        int pos;
        pos = atomicAdd(&g_cursor[d.x], 1); g_csr[pos] = pack_edge(s.x);
        pos = atomicAdd(&g_cursor[d.y], 1); g_csr[pos] = pack_edge(s.y);
        pos = atomicAdd(&g_cursor[d.z], 1); g_csr[pos] = pack_edge(s.z);
        pos = atomicAdd(&g_cursor[d.w], 1); g_csr[pos] = pack_edge(s.w);
    }
}

// ---------------- propagation (unchanged from R14 best) -------------------------
__device__ __forceinline__ void gacc(uint2 u, float w, float4& acc) {
    float2 f0 = __half22float2(*(__half2*)&u.x);
    float2 f1 = __half22float2(*(__half2*)&u.y);
    acc.x = fmaf(f0.x, w, acc.x);
    acc.y = fmaf(f0.y, w, acc.y);
    acc.z = fmaf(f1.x, w, acc.z);
    acc.w = fmaf(f1.y, w, acc.w);
}

__device__ __forceinline__ uint2 pack_h4(float4 v) {
    __half2 o0 = __floats2half2_rn(v.x, v.y);
    __half2 o1 = __floats2half2_rn(v.z, v.w);
    uint2 u;
    u.x = *(unsigned*)&o0;
    u.y = *(unsigned*)&o1;
    return u;
}

__device__ __forceinline__ float4 unpack_h4(uint2 u) {
    float2 f0 = __half22float2(*(__half2*)&u.x);
    float2 f1 = __half22float2(*(__half2*)&u.y);
    return make_float4(f0.x, f0.y, f1.x, f1.y);
}

__device__ __forceinline__ float wt_of(unsigned c) {
    return __half2float(__ushort_as_half((unsigned short)(c & 0xffffu)));
}

template<int MODE>
__global__ void prop_kernel(int dir) {
    const __half* __restrict__ xin  = dir ? g_xh1 : g_xh0;
    __half*       __restrict__ xout = dir ? g_xh0 : g_xh1;

    int node = blockIdx.x * 8 + (threadIdx.x >> 5);
    int lane = threadIdx.x & 31;
    if (node >= N_NODES) return;

    int beg = g_rowstart[node];
    int end = g_rowstart[node + 1];
    int lane4 = lane * 4;

    float4 acc = make_float4(0.f, 0.f, 0.f, 0.f);
    int e = beg;
    for (; e + 8 <= end; e += 8) {
        unsigned c0 = __ldg(&g_csr[e + 0]);
        unsigned c1 = __ldg(&g_csr[e + 1]);
        unsigned c2 = __ldg(&g_csr[e + 2]);
        unsigned c3 = __ldg(&g_csr[e + 3]);
        unsigned c4 = __ldg(&g_csr[e + 4]);
        unsigned c5 = __ldg(&g_csr[e + 5]);
        unsigned c6 = __ldg(&g_csr[e + 6]);
        unsigned c7 = __ldg(&g_csr[e + 7]);
        uint2 u0 = __ldg((const uint2*)(xin + (c0 >> 16) * F_DIM + lane4));
        uint2 u1 = __ldg((const uint2*)(xin + (c1 >> 16) * F_DIM + lane4));
        uint2 u2 = __ldg((const uint2*)(xin + (c2 >> 16) * F_DIM + lane4));
        uint2 u3 = __ldg((const uint2*)(xin + (c3 >> 16) * F_DIM + lane4));
        uint2 u4 = __ldg((const uint2*)(xin + (c4 >> 16) * F_DIM + lane4));
        uint2 u5 = __ldg((const uint2*)(xin + (c5 >> 16) * F_DIM + lane4));
        uint2 u6 = __ldg((const uint2*)(xin + (c6 >> 16) * F_DIM + lane4));
        uint2 u7 = __ldg((const uint2*)(xin + (c7 >> 16) * F_DIM + lane4));
        gacc(u0, wt_of(c0), acc);
        gacc(u1, wt_of(c1), acc);
        gacc(u2, wt_of(c2), acc);
        gacc(u3, wt_of(c3), acc);
        gacc(u4, wt_of(c4), acc);
        gacc(u5, wt_of(c5), acc);
        gacc(u6, wt_of(c6), acc);
        gacc(u7, wt_of(c7), acc);
    }
    for (; e + 2 <= end; e += 2) {
        unsigned c0 = __ldg(&g_csr[e + 0]);
        unsigned c1 = __ldg(&g_csr[e + 1]);
        uint2 u0 = __ldg((const uint2*)(xin + (c0 >> 16) * F_DIM + lane4));
        uint2 u1 = __ldg((const uint2*)(xin + (c1 >> 16) * F_DIM + lane4));
        gacc(u0, wt_of(c0), acc);
        gacc(u1, wt_of(c1), acc);
    }
    for (; e < end; e++) {
        unsigned c = __ldg(&g_csr[e]);
        uint2 u = __ldg((const uint2*)(xin + (c >> 16) * F_DIM + lane4));
        gacc(u, wt_of(c), acc);
    }

    float nd = g_norm[node];
    acc.x *= nd; acc.y *= nd; acc.z *= nd; acc.w *= nd;

    int hoff = node * F_DIM + lane4;
    if (MODE == 0) {
        *(uint2*)(xout + hoff) = pack_h4(acc);
        float4 f = unpack_h4(__ldg((const uint2*)(xin + hoff)));
        f.x += acc.x; f.y += acc.y; f.z += acc.z; f.w += acc.w;
        *(uint2*)(g_yh + hoff) = pack_h4(f);
    } else if (MODE == 1) {
        *(uint2*)(xout + hoff) = pack_h4(acc);
        float4 yv = unpack_h4(*(const uint2*)(g_yh + hoff));
        yv.x += acc.x; yv.y += acc.y; yv.z += acc.z; yv.w += acc.w;
        *(uint2*)(g_yh + hoff) = pack_h4(yv);
    } else {
        float4 yv = unpack_h4(*(const uint2*)(g_yh + hoff));
        yv.x = (yv.x + acc.x) * 0.25f;
        yv.y = (yv.y + acc.y) * 0.25f;
        yv.z = (yv.z + acc.z) * 0.25f;
        yv.w = (yv.w + acc.w) * 0.25f;
        *(uint2*)(xout + hoff) = pack_h4(yv);   // final pre-scaled y -> g_xh1
    }
}

// ---------------- fp16 MMA helper -----------------------------------------------
#define MMA_F16(D, A, B) \
    asm volatile("mma.sync.aligned.m16n8k16.row.col.f32.f16.f16.f32 " \
        "{%0,%1,%2,%3}, {%4,%5,%6,%7}, {%8,%9}, {%0,%1,%2,%3};" \
        : "+f"((D)[0]), "+f"((D)[1]), "+f"((D)[2]), "+f"((D)[3]) \
        : "r"((A)[0]), "r"((A)[1]), "r"((A)[2]), "r"((A)[3]), \
          "r"((B)[0]), "r"((B)[1]))

// ---------------- FUSED MLP: out = logsoftmax( relu(y@W1+b1) @ W2 + b2 ) --------
// 512 threads (16 warps), BM=128, BN=256(=HID); h tile lives only in smem.
// smem layout (dynamic, 125952 B):
static constexpr int AS_OFF = 0;                        // As2 [8][136] half2 = 4352
static constexpr int BS_OFF = 4352;                     // Bs2 [8][264] half2 = 8448
static constexpr int HS_OFF = 12800;                    // hs2 [128][136] half2 = 69632
static constexpr int WS_OFF = 82432;                    // ws2 [128][44] half2 = 22528
static constexpr int LG_OFF = 104960;                   // lg  [128][41] float = 20992
static constexpr int MLP_SMEM = 125952;

__global__ __launch_bounds__(512, 1) void mlp_kernel(const float* __restrict__ b1,
                                                     const float* __restrict__ b2,
                                                     float* __restrict__ out) {
    extern __shared__ __align__(16) char sm[];
    __half2 (*As2)[136] = (__half2(*)[136])(sm + AS_OFF);
    __half2 (*Bs2)[264] = (__half2(*)[264])(sm + BS_OFF);
    __half2 (*hs2)[136] = (__half2(*)[136])(sm + HS_OFF);
    __half2 (*ws2)[44]  = (__half2(*)[44]) (sm + WS_OFF);
    float   (*lg)[41]   = (float(*)[41])   (sm + LG_OFF);

    int tid  = threadIdx.x;
    int lane = tid & 31;
    int wid  = tid >> 5;             // 0..15
    int qrow = lane >> 2;            // 0..7
    int qcol = lane & 3;             // 0..3
    int m0 = blockIdx.x * 128;

    // stage full packed W2 (independent of GEMM1)
    for (int idx = tid; idx < (HID / 2) * NCLS; idx += 512) {
        int p = idx / NCLS, n = idx - p * NCLS;
        ws2[p][n] = g_w2p[idx];
    }

    // ---- GEMM1: 128 x 256 tile ----
    int warp_m = wid & 1;            // 0..1 -> 64 rows
    int warp_n = wid >> 1;           // 0..7 -> 32 cols
    int arow = tid >> 2;             // 0..127
    int akh  = (tid & 3) * 4;        // half index 0,4,8,12

    float d[4][4][4];
#pragma unroll
    for (int t = 0; t < 4; t++)
#pragma unroll
        for (int u = 0; u < 4; u++)
#pragma unroll
            for (int i = 0; i < 4; i++) d[t][u][i] = 0.f;

    for (int k0 = 0; k0 < F_DIM; k0 += 16) {
        // stage A (128 x 16 halves): uint2 per thread
        {
            int gm = m0 + arow;
            uint2 ua = make_uint2(0u, 0u);
            if (gm < N_NODES) ua = *(const uint2*)(g_xh1 + gm * F_DIM + k0 + akh);
            int p = akh >> 1;
            As2[p    ][arow] = *(__half2*)&ua.x;
            As2[p + 1][arow] = *(__half2*)&ua.y;
        }
        // stage B (8 k-pairs x 256 n) from packed W1: uint4 per thread
        {
            int p = tid >> 6;               // 0..7
            int n = (tid & 63) * 4;         // 0..252
            uint4 ub = *(const uint4*)(g_w1p + (k0 / 2 + p) * HID + n);
            Bs2[p][n + 0] = *(__half2*)&ub.x;
            Bs2[p][n + 1] = *(__half2*)&ub.y;
            Bs2[p][n + 2] = *(__half2*)&ub.z;
            Bs2[p][n + 3] = *(__half2*)&ub.w;
        }
        __syncthreads();

        {
            unsigned a[4][4], b[4][2];
#pragma unroll
            for (int t = 0; t < 4; t++) {
                int mr = warp_m * 64 + t * 16 + qrow;
                a[t][0] = *(unsigned*)&As2[qcol][mr];
                a[t][1] = *(unsigned*)&As2[qcol][mr + 8];
                a[t][2] = *(unsigned*)&As2[qcol + 4][mr];
                a[t][3] = *(unsigned*)&As2[qcol + 4][mr + 8];
            }
#pragma unroll
            for (int u = 0; u < 4; u++) {
                int bcol = warp_n * 32 + u * 8 + qrow;
                b[u][0] = *(unsigned*)&Bs2[qcol][bcol];
                b[u][1] = *(unsigned*)&Bs2[qcol + 4][bcol];
            }
#pragma unroll
            for (int t = 0; t < 4; t++)
#pragma unroll
                for (int u = 0; u < 4; u++)
                    MMA_F16(d[t][u], a[t], b[u]);
        }
        __syncthreads();
    }

    // GEMM1 epilogue: bias + relu -> hs2 (fp16 pair layout, local rows)
#pragma unroll
    for (int t = 0; t < 4; t++) {
        int r0 = warp_m * 64 + t * 16 + qrow;   // local row
#pragma unroll
        for (int u = 0; u < 4; u++) {
            int c = warp_n * 32 + u * 8 + qcol * 2;
            float2 bb = *(const float2*)&b1[c];
            hs2[c >> 1][r0]     = __floats2half2_rn(fmaxf(d[t][u][0] + bb.x, 0.f),
                                                    fmaxf(d[t][u][1] + bb.y, 0.f));
            hs2[c >> 1][r0 + 8] = __floats2half2_rn(fmaxf(d[t][u][2] + bb.x, 0.f),
                                                    fmaxf(d[t][u][3] + bb.y, 0.f));
        }
    }
    __syncthreads();

    // ---- GEMM2: warps 0..7, each 16 rows, full K=256, 5 n-tiles ----
    if (wid < 8) {
        float e2[5][4];
#pragma unroll
        for (int u = 0; u < 5; u++)
#pragma unroll
            for (int i = 0; i < 4; i++) e2[u][i] = 0.f;

        int mr = wid * 16 + qrow;
#pragma unroll
        for (int ks = 0; ks < 16; ks++) {
            int kA = ks * 8 + qcol;
            unsigned a[4];
            a[0] = *(unsigned*)&hs2[kA][mr];
            a[1] = *(unsigned*)&hs2[kA][mr + 8];
            a[2] = *(unsigned*)&hs2[kA + 4][mr];
            a[3] = *(unsigned*)&hs2[kA + 4][mr + 8];
#pragma unroll
            for (int u = 0; u < 5; u++) {
                unsigned b[2];
                b[0] = *(unsigned*)&ws2[kA][u * 8 + qrow];
                b[1] = *(unsigned*)&ws2[kA + 4][u * 8 + qrow];
                MMA_F16(e2[u], a, b);
            }
        }
#pragma unroll
        for (int u = 0; u < 5; u++) {
            int c = u * 8 + qcol * 2;
            float2 bb = *(const float2*)&b2[c];
            lg[mr][c]         = e2[u][0] + bb.x;
            lg[mr][c + 1]     = e2[u][1] + bb.y;
            lg[mr + 8][c]     = e2[u][2] + bb.x;
            lg[mr + 8][c + 1] = e2[u][3] + bb.y;
        }
    }
    __syncthreads();

    // log_softmax
    if (tid < 128) {
        int row = m0 + tid;
        if (row < N_NODES) {
            float m = -1e30f;
#pragma unroll
            for (int c = 0; c < NCLS; c++) m = fmaxf(m, lg[tid][c]);
            float s = 0.f;
#pragma unroll
            for (int c = 0; c < NCLS; c++) s += expf(lg[tid][c] - m);
            float sub = m + logf(s);
            float* orow = &out[row * NCLS];
#pragma unroll
            for (int c = 0; c < NCLS; c++) orow[c] = lg[tid][c] - sub;
        }
    }
}

// ---------------- launch ----------------
extern "C" void kernel_launch(void* const* d_in, const int* in_sizes, int n_in,
                              void* d_out, int out_size) {
    const float* features = (const float*)d_in[0];
    const int*   src      = (const int*)d_in[1];
    const int*   dst      = (const int*)d_in[2];
    const float* W1       = (const float*)d_in[3];
    const float* b1       = (const float*)d_in[4];
    const float* W2       = (const float*)d_in[5];
    const float* b2       = (const float*)d_in[6];
    float*       out      = (float*)d_out;

    const int NB  = (N_NODES + 255) / 256;      // 196
    const int E4B = (N_EDGES / 4 + 255) / 256;  // 782
    const int PB  = (N_NODES + 7) / 8;          // 6250
    const float4* feat4 = (const float4*)features;

    cudaFuncSetAttribute(mlp_kernel, cudaFuncAttributeMaxDynamicSharedMemorySize,
                         MLP_SMEM);

    zero_deg_kernel<<<NB, 256>>>();
    deg_kernel<<<E4B, 256>>>((const int4*)dst);
    scan1_kernel<<<SCAN_BLOCKS, 256>>>();
    scan3_kernel<<<6 * SCAN_BLOCKS, 256>>>(feat4, W1, W2);
    fill_kernel<<<E4B, 256>>>((const int4*)src, (const int4*)dst);

    prop_kernel<0><<<PB, 256>>>(0);   // x0 -> x1, y = x0 + x1
    prop_kernel<1><<<PB, 256>>>(1);   // x1 -> x0, y += x2
    prop_kernel<2><<<PB, 256>>>(0);   // x0(x2) -> final y/4 into g_xh1

    const int MB = (N_NODES + 127) / 128;       // 391
    mlp_kernel<<<MB, 512, MLP_SMEM>>>(b1, b2, out);
}

// round 16
// speedup vs baseline: 1.3198x; 1.3198x over previous
#include <cuda_runtime.h>
#include <cuda_fp16.h>
#include <math.h>

#define N_NODES 50000
#define N_EDGES 800000
#define F_DIM   128
#define F4      32      // float4 per feature row
#define HID     256
#define NCLS    40

#define SCAN_BLOCKS ((N_NODES + 255) / 256)   // 196

// ---------------- device scratch (static: no allocation allowed) ----------------
// RULE (learned R3-R5): never pass __device__ symbol addresses from host code —
// on GB300 the host-side shadow resolves via ATS to HOST memory. All buffer
// selection happens inside device code.
// RULE (learned R15): do NOT fuse the two GEMMs under one giant-smem kernel —
// 1 CTA/SM + phase serialization loses ~45us vs separate kernels.
__device__ int      g_deg[N_NODES];
__device__ int      g_rowstart[N_NODES + 1];
__device__ int      g_cursor[N_NODES];
__device__ int      g_bsum[SCAN_BLOCKS];
__device__ float    g_norm[N_NODES];
__device__ unsigned g_csr[N_EDGES];          // (src << 16) | fp16(norm[src]) bits
__device__ __half   g_xh0[N_NODES * F_DIM];  // fp16 ping
__device__ __half   g_xh1[N_NODES * F_DIM];  // fp16 pong; holds final fp16 y
__device__ __half   g_yh [N_NODES * F_DIM];  // fp16 running sum (fp32 math)
__device__ __half   g_h  [N_NODES * HID];    // fp16 hidden activations
__device__ __half2  g_w1p[(F_DIM / 2) * HID];   // W1 packed (k,k+1) pairs
__device__ __half2  g_w2p[(HID / 2) * NCLS];    // W2 packed (k,k+1) pairs

// ---------------- build: degree ----------------
__global__ void zero_deg_kernel() {
    int i = blockIdx.x * blockDim.x + threadIdx.x;
    if (i < N_NODES) g_deg[i] = 0;
}

__global__ void deg_kernel(const int4* __restrict__ dst4) {
    int i = blockIdx.x * blockDim.x + threadIdx.x;
    if (i < N_EDGES / 4) {
        int4 d = dst4[i];
        atomicAdd(&g_deg[d.x], 1);
        atomicAdd(&g_deg[d.y], 1);
        atomicAdd(&g_deg[d.z], 1);
        atomicAdd(&g_deg[d.w], 1);
    }
}

// ---------------- hierarchical scan ----------------
__device__ __forceinline__ int warp_incl_scan(int v, int lane) {
#pragma unroll
    for (int o = 1; o < 32; o <<= 1) {
        int n = __shfl_up_sync(0xffffffffu, v, o);
        if (lane >= o) v += n;
    }
    return v;
}

__device__ __forceinline__ int block_incl_scan_256(int v, int tid) {
    __shared__ int ws[8];
    int lane = tid & 31, w = tid >> 5;
    int incl = warp_incl_scan(v, lane);
    if (lane == 31) ws[w] = incl;
    __syncthreads();
    if (w == 0) {
        int s = (lane < 8) ? ws[lane] : 0;
        s = warp_incl_scan(s, lane);
        if (lane < 8) ws[lane] = s;
    }
    __syncthreads();
    if (w > 0) incl += ws[w - 1];
    return incl;
}

__global__ void scan1_kernel() {
    int tid = threadIdx.x;
    int i = blockIdx.x * 256 + tid;
    int v = (i < N_NODES) ? g_deg[i] : 0;
    if (i < N_NODES) g_norm[i] = rsqrtf((float)(v < 1 ? 1 : v));
    int incl = block_incl_scan_256(v, tid);
    if (i < N_NODES) g_rowstart[i] = incl - v;
    if (tid == 255) g_bsum[blockIdx.x] = incl;
}

// phase 2: blocks < SCAN_BLOCKS do offset fixup; ALL blocks (grid-stride)
// convert features to fp16 and pack W1/W2 into fp16 pair layout
__global__ void scan3_kernel(const float4* __restrict__ feat,
                             const float* __restrict__ W1,
                             const float* __restrict__ W2) {
    __shared__ int ssum[8];
    int tid = threadIdx.x;
    int bid = blockIdx.x;
    int lane = tid & 31, w = tid >> 5;

    if (bid < SCAN_BLOCKS) {
        int v = (tid < bid && tid < SCAN_BLOCKS) ? g_bsum[tid] : 0;
#pragma unroll
        for (int o = 16; o > 0; o >>= 1) v += __shfl_down_sync(0xffffffffu, v, o);
        if (lane == 0) ssum[w] = v;
        __syncthreads();
        if (tid == 0) {
            int s = 0;
#pragma unroll
            for (int i = 0; i < 8; i++) s += ssum[i];
            ssum[0] = s;
        }
        __syncthreads();
        int off = ssum[0];

        int i = bid * 256 + tid;
        if (i < N_NODES) {
            int r = g_rowstart[i] + off;
            g_rowstart[i] = r;
            g_cursor[i]   = r;
        }
        if (i == 0) g_rowstart[N_NODES] = N_EDGES;
    }

    int gid = bid * 256 + tid;
    int stride = gridDim.x * 256;

    // grid-stride fp16 conversion of features
    uint2* xh0v = (uint2*)g_xh0;
    for (int j = gid; j < N_NODES * F4; j += stride) {
        float4 f = feat[j];
        __half2 h0 = __floats2half2_rn(f.x, f.y);
        __half2 h1 = __floats2half2_rn(f.z, f.w);
        uint2 u;
        u.x = *(unsigned*)&h0;
        u.y = *(unsigned*)&h1;
        xh0v[j] = u;
    }
    // pack W1 -> (k,k+1)-pair fp16 layout [F_DIM/2][HID]
    for (int j = gid; j < (F_DIM / 2) * HID; j += stride) {
        int p = j / HID, n = j - p * HID;
        g_w1p[j] = __floats2half2_rn(W1[(2 * p) * HID + n], W1[(2 * p + 1) * HID + n]);
    }
    // pack W2 -> [HID/2][NCLS]
    for (int j = gid; j < (HID / 2) * NCLS; j += stride) {
        int p = j / NCLS, n = j - p * NCLS;
        g_w2p[j] = __floats2half2_rn(W2[(2 * p) * NCLS + n], W2[(2 * p + 1) * NCLS + n]);
    }
}

// fill CSR: packed (src<<16)|fp16(norm[src]), int4 edge loads
__device__ __forceinline__ unsigned pack_edge(int s) {
    __half hw = __float2half_rn(g_norm[s]);
    return ((unsigned)s << 16) | (unsigned)__half_as_ushort(hw);
}

__global__ void fill_kernel(const int4* __restrict__ src4, const int4* __restrict__ dst4) {
    int i = blockIdx.x * blockDim.x + threadIdx.x;
    if (i < N_EDGES / 4) {
        int4 s = src4[i];
        int4 d = dst4[i];
        int pos;
        pos = atomicAdd(&g_cursor[d.x], 1); g_csr[pos] = pack_edge(s.x);
        pos = atomicAdd(&g_cursor[d.y], 1); g_csr[pos] = pack_edge(s.y);
        pos = atomicAdd(&g_cursor[d.z], 1); g_csr[pos] = pack_edge(s.z);
        pos = atomicAdd(&g_cursor[d.w], 1); g_csr[pos] = pack_edge(s.w);
    }
}

// ---------------- propagation (R14 best, unchanged) ------------------------------
__device__ __forceinline__ void gacc(uint2 u, float w, float4& acc) {
    float2 f0 = __half22float2(*(__half2*)&u.x);
    float2 f1 = __half22float2(*(__half2*)&u.y);
    acc.x = fmaf(f0.x, w, acc.x);
    acc.y = fmaf(f0.y, w, acc.y);
    acc.z = fmaf(f1.x, w, acc.z);
    acc.w = fmaf(f1.y, w, acc.w);
}

__device__ __forceinline__ uint2 pack_h4(float4 v) {
    __half2 o0 = __floats2half2_rn(v.x, v.y);
    __half2 o1 = __floats2half2_rn(v.z, v.w);
    uint2 u;
    u.x = *(unsigned*)&o0;
    u.y = *(unsigned*)&o1;
    return u;
}

__device__ __forceinline__ float4 unpack_h4(uint2 u) {
    float2 f0 = __half22float2(*(__half2*)&u.x);
    float2 f1 = __half22float2(*(__half2*)&u.y);
    return make_float4(f0.x, f0.y, f1.x, f1.y);
}

__device__ __forceinline__ float wt_of(unsigned c) {
    return __half2float(__ushort_as_half((unsigned short)(c & 0xffffu)));
}

template<int MODE>
__global__ void prop_kernel(int dir) {
    const __half* __restrict__ xin  = dir ? g_xh1 : g_xh0;
    __half*       __restrict__ xout = dir ? g_xh0 : g_xh1;

    int node = blockIdx.x * 8 + (threadIdx.x >> 5);
    int lane = threadIdx.x & 31;
    if (node >= N_NODES) return;

    int beg = g_rowstart[node];
    int end = g_rowstart[node + 1];
    int lane4 = lane * 4;

    float4 acc = make_float4(0.f, 0.f, 0.f, 0.f);
    int e = beg;
    for (; e + 8 <= end; e += 8) {
        unsigned c0 = __ldg(&g_csr[e + 0]);
        unsigned c1 = __ldg(&g_csr[e + 1]);
        unsigned c2 = __ldg(&g_csr[e + 2]);
        unsigned c3 = __ldg(&g_csr[e + 3]);
        unsigned c4 = __ldg(&g_csr[e + 4]);
        unsigned c5 = __ldg(&g_csr[e + 5]);
        unsigned c6 = __ldg(&g_csr[e + 6]);
        unsigned c7 = __ldg(&g_csr[e + 7]);
        uint2 u0 = __ldg((const uint2*)(xin + (c0 >> 16) * F_DIM + lane4));
        uint2 u1 = __ldg((const uint2*)(xin + (c1 >> 16) * F_DIM + lane4));
        uint2 u2 = __ldg((const uint2*)(xin + (c2 >> 16) * F_DIM + lane4));
        uint2 u3 = __ldg((const uint2*)(xin + (c3 >> 16) * F_DIM + lane4));
        uint2 u4 = __ldg((const uint2*)(xin + (c4 >> 16) * F_DIM + lane4));
        uint2 u5 = __ldg((const uint2*)(xin + (c5 >> 16) * F_DIM + lane4));
        uint2 u6 = __ldg((const uint2*)(xin + (c6 >> 16) * F_DIM + lane4));
        uint2 u7 = __ldg((const uint2*)(xin + (c7 >> 16) * F_DIM + lane4));
        gacc(u0, wt_of(c0), acc);
        gacc(u1, wt_of(c1), acc);
        gacc(u2, wt_of(c2), acc);
        gacc(u3, wt_of(c3), acc);
        gacc(u4, wt_of(c4), acc);
        gacc(u5, wt_of(c5), acc);
        gacc(u6, wt_of(c6), acc);
        gacc(u7, wt_of(c7), acc);
    }
    for (; e + 2 <= end; e += 2) {
        unsigned c0 = __ldg(&g_csr[e + 0]);
        unsigned c1 = __ldg(&g_csr[e + 1]);
        uint2 u0 = __ldg((const uint2*)(xin + (c0 >> 16) * F_DIM + lane4));
        uint2 u1 = __ldg((const uint2*)(xin + (c1 >> 16) * F_DIM + lane4));
        gacc(u0, wt_of(c0), acc);
        gacc(u1, wt_of(c1), acc);
    }
    for (; e < end; e++) {
        unsigned c = __ldg(&g_csr[e]);
        uint2 u = __ldg((const uint2*)(xin + (c >> 16) * F_DIM + lane4));
        gacc(u, wt_of(c), acc);
    }

    float nd = g_norm[node];
    acc.x *= nd; acc.y *= nd; acc.z *= nd; acc.w *= nd;

    int hoff = node * F_DIM + lane4;
    if (MODE == 0) {
        *(uint2*)(xout + hoff) = pack_h4(acc);
        float4 f = unpack_h4(__ldg((const uint2*)(xin + hoff)));
        f.x += acc.x; f.y += acc.y; f.z += acc.z; f.w += acc.w;
        *(uint2*)(g_yh + hoff) = pack_h4(f);
    } else if (MODE == 1) {
        *(uint2*)(xout + hoff) = pack_h4(acc);
        float4 yv = unpack_h4(*(const uint2*)(g_yh + hoff));
        yv.x += acc.x; yv.y += acc.y; yv.z += acc.z; yv.w += acc.w;
        *(uint2*)(g_yh + hoff) = pack_h4(yv);
    } else {
        float4 yv = unpack_h4(*(const uint2*)(g_yh + hoff));
        yv.x = (yv.x + acc.x) * 0.25f;
        yv.y = (yv.y + acc.y) * 0.25f;
        yv.z = (yv.z + acc.z) * 0.25f;
        yv.w = (yv.w + acc.w) * 0.25f;
        *(uint2*)(xout + hoff) = pack_h4(yv);   // final pre-scaled y -> g_xh1
    }
}

// ---------------- fp16 MMA helper -----------------------------------------------
#define MMA_F16(D, A, B) \
    asm volatile("mma.sync.aligned.m16n8k16.row.col.f32.f16.f16.f32 " \
        "{%0,%1,%2,%3}, {%4,%5,%6,%7}, {%8,%9}, {%0,%1,%2,%3};" \
        : "+f"((D)[0]), "+f"((D)[1]), "+f"((D)[2]), "+f"((D)[3]) \
        : "r"((A)[0]), "r"((A)[1]), "r"((A)[2]), "r"((A)[3]), \
          "r"((B)[0]), "r"((B)[1]))

// ---------------- GEMM1 (fp16 MMA): h = relu( y16 @ W1 + b1 ) -------------------
// BM=128, BN=128, BK=16, 256 threads = 8 warps (2m x 4n), warp tile 64x32
// B staged from pre-packed g_w1p via uint4 copies (no cvt, half traffic)
__global__ __launch_bounds__(256) void gemm1_kernel(const float* __restrict__ b1) {
    __shared__ __half2 As2[8][132];   // [k2][m]
    __shared__ __half2 Bs2[8][132];   // [k2][n]

    int tid  = threadIdx.x;
    int lane = tid & 31;
    int wid  = tid >> 5;
    int warp_m = wid & 1;
    int warp_n = wid >> 1;
    int qrow = lane >> 2;
    int qcol = lane & 3;

    int m0 = blockIdx.x * 128;
    int n0 = blockIdx.y * 128;

    int arow = tid >> 1;             // 0..127
    int ak   = (tid & 1) * 8;        // halves 0 or 8

    // B staging coords: 8 k-pairs x 128 n / 4-per-thread = 256 threads
    int bp = tid >> 5;               // k-pair 0..7
    int bn = (tid & 31) * 4;         // n 0..124

    float d[4][4][4];
#pragma unroll
    for (int t = 0; t < 4; t++)
#pragma unroll
        for (int u = 0; u < 4; u++)
#pragma unroll
            for (int i = 0; i < 4; i++) d[t][u][i] = 0.f;

    for (int k0 = 0; k0 < F_DIM; k0 += 16) {
        {
            int gm = m0 + arow;
            uint4 u = make_uint4(0u, 0u, 0u, 0u);
            if (gm < N_NODES) u = *(const uint4*)(g_xh1 + gm * F_DIM + k0 + ak);
            int p = ak >> 1;
            As2[p + 0][arow] = *(__half2*)&u.x;
            As2[p + 1][arow] = *(__half2*)&u.y;
            As2[p + 2][arow] = *(__half2*)&u.z;
            As2[p + 3][arow] = *(__half2*)&u.w;
        }
        {
            uint4 ub = *(const uint4*)(g_w1p + (k0 / 2 + bp) * HID + n0 + bn);
            Bs2[bp][bn + 0] = *(__half2*)&ub.x;
            Bs2[bp][bn + 1] = *(__half2*)&ub.y;
            Bs2[bp][bn + 2] = *(__half2*)&ub.z;
            Bs2[bp][bn + 3] = *(__half2*)&ub.w;
        }
        __syncthreads();

        {
            unsigned a[4][4], b[4][2];
#pragma unroll
            for (int t = 0; t < 4; t++) {
                int mr = warp_m * 64 + t * 16 + qrow;
                a[t][0] = *(unsigned*)&As2[qcol][mr];
                a[t][1] = *(unsigned*)&As2[qcol][mr + 8];
                a[t][2] = *(unsigned*)&As2[qcol + 4][mr];
                a[t][3] = *(unsigned*)&As2[qcol + 4][mr + 8];
            }
#pragma unroll
            for (int u = 0; u < 4; u++) {
                int bcol = warp_n * 32 + u * 8 + qrow;
                b[u][0] = *(unsigned*)&Bs2[qcol][bcol];
                b[u][1] = *(unsigned*)&Bs2[qcol + 4][bcol];
            }
#pragma unroll
            for (int t = 0; t < 4; t++)
#pragma unroll
                for (int u = 0; u < 4; u++)
                    MMA_F16(d[t][u], a[t], b[u]);
        }
        __syncthreads();
    }

#pragma unroll
    for (int t = 0; t < 4; t++) {
        int r0 = m0 + warp_m * 64 + t * 16 + qrow;
#pragma unroll
        for (int u = 0; u < 4; u++) {
            int c = n0 + warp_n * 32 + u * 8 + qcol * 2;
            float2 bb = *(const float2*)&b1[c];
            if (r0 < N_NODES) {
                __half2 o = __floats2half2_rn(fmaxf(d[t][u][0] + bb.x, 0.f),
                                              fmaxf(d[t][u][1] + bb.y, 0.f));
                *(__half2*)(g_h + r0 * HID + c) = o;
            }
            if (r0 + 8 < N_NODES) {
                __half2 o = __floats2half2_rn(fmaxf(d[t][u][2] + bb.x, 0.f),
                                              fmaxf(d[t][u][3] + bb.y, 0.f));
                *(__half2*)(g_h + (r0 + 8) * HID + c) = o;
            }
        }
    }
}

// ---------------- GEMM2 (fp16 MMA) + fused log_softmax --------------------------
__global__ __launch_bounds__(256) void gemm2_kernel(const float* __restrict__ b2,
                                                    float* __restrict__ out) {
    __shared__ __half2 hs2[16][132];
    __shared__ __half2 ws2[16][44];
    __shared__ float   lg[128][41];

    int tid  = threadIdx.x;
    int lane = tid & 31;
    int wid  = tid >> 5;
    int qrow = lane >> 2;
    int qcol = lane & 3;
    int m0 = blockIdx.x * 128;

    float d[5][4];
#pragma unroll
    for (int u = 0; u < 5; u++)
#pragma unroll
        for (int i = 0; i < 4; i++) d[u][i] = 0.f;

    int arow = tid >> 1;
    int ak   = (tid & 1) * 16;

    for (int k0 = 0; k0 < HID; k0 += 32) {
        {
            int gm = m0 + arow;
            const __half* hp = g_h + gm * HID + k0 + ak;
            uint4 v0 = make_uint4(0u, 0u, 0u, 0u), v1 = v0;
            if (gm < N_NODES) {
                v0 = *(const uint4*)hp;
                v1 = *(const uint4*)(hp + 8);
            }
            int k2b = ak >> 1;
            hs2[k2b + 0][arow] = *(__half2*)&v0.x;
            hs2[k2b + 1][arow] = *(__half2*)&v0.y;
            hs2[k2b + 2][arow] = *(__half2*)&v0.z;
            hs2[k2b + 3][arow] = *(__half2*)&v0.w;
            hs2[k2b + 4][arow] = *(__half2*)&v1.x;
            hs2[k2b + 5][arow] = *(__half2*)&v1.y;
            hs2[k2b + 6][arow] = *(__half2*)&v1.z;
            hs2[k2b + 7][arow] = *(__half2*)&v1.w;
        }
        // stage packed W2 chunk: 16 k-pairs x 40 n
        for (int idx = tid; idx < 16 * NCLS; idx += 256) {
            int p = idx / NCLS, n = idx - p * NCLS;
            ws2[p][n] = g_w2p[(k0 / 2 + p) * NCLS + n];
        }
        __syncthreads();

#pragma unroll
        for (int ks = 0; ks < 2; ks++) {
            int kA = ks * 8 + qcol;
            int mr = wid * 16 + qrow;
            unsigned a[4];
            a[0] = *(unsigned*)&hs2[kA][mr];
            a[1] = *(unsigned*)&hs2[kA][mr + 8];
            a[2] = *(unsigned*)&hs2[kA + 4][mr];
            a[3] = *(unsigned*)&hs2[kA + 4][mr + 8];
#pragma unroll
            for (int u = 0; u < 5; u++) {
                unsigned b[2];
                b[0] = *(unsigned*)&ws2[kA][u * 8 + qrow];
                b[1] = *(unsigned*)&ws2[kA + 4][u * 8 + qrow];
                MMA_F16(d[u], a, b);
            }
        }
        __syncthreads();
    }

    {
        int mr = wid * 16 + qrow;
#pragma unroll
        for (int u = 0; u < 5; u++) {
            int c = u * 8 + qcol * 2;
            float2 bb = *(const float2*)&b2[c];
            lg[mr][c]         = d[u][0] + bb.x;
            lg[mr][c + 1]     = d[u][1] + bb.y;
            lg[mr + 8][c]     = d[u][2] + bb.x;
            lg[mr + 8][c + 1] = d[u][3] + bb.y;
        }
    }
    __syncthreads();

    if (tid < 128) {
        int row = m0 + tid;
        if (row < N_NODES) {
            float m = -1e30f;
#pragma unroll
            for (int c = 0; c < NCLS; c++) m = fmaxf(m, lg[tid][c]);
            float s = 0.f;
#pragma unroll
            for (int c = 0; c < NCLS; c++) s += expf(lg[tid][c] - m);
            float sub = m + logf(s);
            float* orow = &out[row * NCLS];
#pragma unroll
            for (int c = 0; c < NCLS; c++) orow[c] = lg[tid][c] - sub;
        }
    }
}

// ---------------- launch ----------------
extern "C" void kernel_launch(void* const* d_in, const int* in_sizes, int n_in,
                              void* d_out, int out_size) {
    const float* features = (const float*)d_in[0];
    const int*   src      = (const int*)d_in[1];
    const int*   dst      = (const int*)d_in[2];
    const float* W1       = (const float*)d_in[3];
    const float* b1       = (const float*)d_in[4];
    const float* W2       = (const float*)d_in[5];
    const float* b2       = (const float*)d_in[6];
    float*       out      = (float*)d_out;

    const int NB  = (N_NODES + 255) / 256;      // 196
    const int E4B = (N_EDGES / 4 + 255) / 256;  // 782
    const int PB  = (N_NODES + 7) / 8;          // 6250
    const float4* feat4 = (const float4*)features;

    zero_deg_kernel<<<NB, 256>>>();
    deg_kernel<<<E4B, 256>>>((const int4*)dst);
    scan1_kernel<<<SCAN_BLOCKS, 256>>>();
    scan3_kernel<<<6 * SCAN_BLOCKS, 256>>>(feat4, W1, W2);
    fill_kernel<<<E4B, 256>>>((const int4*)src, (const int4*)dst);

    prop_kernel<0><<<PB, 256>>>(0);   // x0 -> x1, y = x0 + x1
    prop_kernel<1><<<PB, 256>>>(1);   // x1 -> x0, y += x2
    prop_kernel<2><<<PB, 256>>>(0);   // x0(x2) -> final y/4 into g_xh1

    dim3 g1((N_NODES + 127) / 128, HID / 128);  // (391, 2)
    gemm1_kernel<<<g1, 256>>>(b1);

    const int G2B = (N_NODES + 127) / 128;      // 391
    gemm2_kernel<<<G2B, 256>>>(b2, out);
}